// round 16
// baseline (speedup 1.0000x reference)
#include <cuda_runtime.h>
#include <cuda_bf16.h>
#include <cstdint>

#define CM_B    64
#define CM_T    256
#define CM_NI   512
#define CM_NO   512
#define CM_NOBS 128
#define ETA     0.01f

typedef unsigned long long u64;

// Scratch: C[b][m][n], m<256 -> G[s=m][t=n]; m>=256 -> P0[o=m-256][t=n]
__device__ float g_scratch[(size_t)CM_B * 384 * 256];
// Prepacked bf16 hi/lo operands (X in [b][t][k] order, W_obs gathered in [b][j][k])
__device__ __nv_bfloat16 g_XH[(size_t)CM_B * CM_T * CM_NI];
__device__ __nv_bfloat16 g_XL[(size_t)CM_B * CM_T * CM_NI];
__device__ __nv_bfloat16 g_WH[(size_t)CM_B * CM_NOBS * CM_NI];
__device__ __nv_bfloat16 g_WL[(size_t)CM_B * CM_NOBS * CM_NI];

// ---------------- helpers ----------------
__device__ __forceinline__ u64 pk2(float lo, float hi) {
    u64 r; asm("mov.b64 %0, {%1, %2};" : "=l"(r) : "f"(lo), "f"(hi)); return r;
}
__device__ __forceinline__ float2 upk2(u64 v) {
    float2 f; asm("mov.b64 {%0, %1}, %2;" : "=f"(f.x), "=f"(f.y) : "l"(v)); return f;
}
__device__ __forceinline__ u64 ffma2(u64 a, u64 b, u64 c) {
    u64 d; asm("fma.rn.f32x2 %0, %1, %2, %3;" : "=l"(d) : "l"(a), "l"(b), "l"(c)); return d;
}
__device__ __forceinline__ float sigmoidf_fast(float v) {
    return __fdividef(1.0f, 1.0f + __expf(-v));
}
__device__ __forceinline__ uint32_t bf2u(__nv_bfloat162 v) {
    return reinterpret_cast<uint32_t&>(v);
}
__device__ __forceinline__ uint32_t smem_u32(const void* p) {
    uint32_t a;
    asm("{ .reg .u64 t; cvta.to.shared.u64 t, %1; cvt.u32.u64 %0, t; }" : "=r"(a) : "l"(p));
    return a;
}
__device__ __forceinline__ void cp16(uint32_t saddr, const void* gptr) {
    asm volatile("cp.async.ca.shared.global [%0], [%1], 16;" :: "r"(saddr), "l"(gptr));
}
#define CP_COMMIT() asm volatile("cp.async.commit_group;" ::: "memory")
#define CP_WAIT0()  asm volatile("cp.async.wait_group 0;"  ::: "memory")

// mma m16n8k16 bf16, D += A*B
__device__ __forceinline__ void mma16(float& d0, float& d1, float& d2, float& d3,
                                      uint32_t a0, uint32_t a1, uint32_t a2, uint32_t a3,
                                      uint32_t b0, uint32_t b1) {
    asm volatile(
        "mma.sync.aligned.m16n8k16.row.col.f32.bf16.bf16.f32 "
        "{%0,%1,%2,%3}, {%4,%5,%6,%7}, {%8,%9}, {%0,%1,%2,%3};"
        : "+f"(d0), "+f"(d1), "+f"(d2), "+f"(d3)
        : "r"(a0), "r"(a1), "r"(a2), "r"(a3), "r"(b0), "r"(b1));
}

// ---------------- Kernel 0: prep — fp32 -> bf16 hi/lo split, W gathered ----------------
#define NX4 (CM_B * CM_T * CM_NI / 4)      // 2,097,152 float4 groups
#define NW4 (CM_B * CM_NOBS * CM_NI / 4)   // 1,048,576

__global__ __launch_bounds__(256)
void prep_kernel(const float* __restrict__ X,
                 const float* __restrict__ Wi,
                 const int*   __restrict__ obs) {
    const int idx = blockIdx.x * 256 + threadIdx.x;
    float4 v;
    __nv_bfloat16 *dh, *dl;
    if (idx < NX4) {
        v  = __ldg((const float4*)X + idx);
        dh = g_XH + (size_t)idx * 4;
        dl = g_XL + (size_t)idx * 4;
    } else {
        const int id2 = idx - NX4;
        const int k4 = id2 & 127;
        const int j  = (id2 >> 7) & 127;
        const int b  = id2 >> 14;
        v  = __ldg((const float4*)(Wi + ((size_t)b * CM_NO + __ldg(&obs[j])) * CM_NI) + k4);
        dh = g_WH + (size_t)id2 * 4;
        dl = g_WL + (size_t)id2 * 4;
    }
    __nv_bfloat162 h0 = __floats2bfloat162_rn(v.x, v.y);
    __nv_bfloat162 h1 = __floats2bfloat162_rn(v.z, v.w);
    float2 f0 = __bfloat1622float2(h0), f1 = __bfloat1622float2(h1);
    __nv_bfloat162 l0 = __floats2bfloat162_rn(v.x - f0.x, v.y - f0.y);
    __nv_bfloat162 l1 = __floats2bfloat162_rn(v.z - f1.x, v.w - f1.y);
    *(uint2*)dh = make_uint2(bf2u(h0), bf2u(h1));
    *(uint2*)dl = make_uint2(bf2u(l0), bf2u(l1));
}

// ---------------- Kernel 1: batched GEMM C = [X;W_obs] * X^T (bf16x3, prepacked) ----------------
#define KC   32
#define NCH  (CM_NI / KC)     // 16 chunks
#define SBF  40               // bf16 row stride (80B): conflict-free fragment pattern

__constant__ int c_mt[5] = {0, 0, 1, 2, 2};
__constant__ int c_nt[5] = {0, 1, 1, 0, 1};

__global__ __launch_bounds__(256)
void gemm_kernel(int dummy) {
    __shared__ __align__(16) __nv_bfloat16 Ah[128 * SBF], Al[128 * SBF];
    __shared__ __align__(16) __nv_bfloat16 Bh[128 * SBF], Bl[128 * SBF];

    const int b     = blockIdx.x;
    const int mtile = c_mt[blockIdx.y];
    const int ntile = c_nt[blockIdx.y];

    const int tid  = threadIdx.x;
    const int warp = tid >> 5, lane = tid & 31;
    const int wm   = warp >> 1, wn = warp & 1;      // 4x2 warps over 128x128
    const int gID  = lane >> 2, tig = lane & 3;

    // prepacked row bases (W is already gathered in j order)
    const __nv_bfloat16* aBH = (mtile < 2)
        ? g_XH + ((size_t)b * CM_T + mtile * 128) * CM_NI
        : g_WH + (size_t)b * CM_NOBS * CM_NI;
    const __nv_bfloat16* aBL = (mtile < 2)
        ? g_XL + ((size_t)b * CM_T + mtile * 128) * CM_NI
        : g_WL + (size_t)b * CM_NOBS * CM_NI;
    const __nv_bfloat16* bBH = g_XH + ((size_t)b * CM_T + ntile * 128) * CM_NI;
    const __nv_bfloat16* bBL = g_XL + ((size_t)b * CM_T + ntile * 128) * CM_NI;

    // staging role: 2 threads per row, 16 bf16 (32B) each
    const int srow = tid >> 1;
    const int scq  = (tid & 1) * 16;

    float acc[2][8][4];
    #pragma unroll
    for (int i = 0; i < 2; ++i)
        #pragma unroll
        for (int j = 0; j < 8; ++j)
            #pragma unroll
            for (int q = 0; q < 4; ++q) acc[i][j][q] = 0.f;

    for (int c = 0; c < NCH; ++c) {
        const size_t gofs = (size_t)srow * CM_NI + c * KC + scq;
        const uint32_t sofs = smem_u32(Ah) + (srow * SBF + scq) * 2 - smem_u32(Ah); // elem->byte below
        const uint32_t so = (uint32_t)((srow * SBF + scq) * 2);
        cp16(smem_u32(Ah) + so,      aBH + gofs);
        cp16(smem_u32(Ah) + so + 16, aBH + gofs + 8);
        cp16(smem_u32(Al) + so,      aBL + gofs);
        cp16(smem_u32(Al) + so + 16, aBL + gofs + 8);
        cp16(smem_u32(Bh) + so,      bBH + gofs);
        cp16(smem_u32(Bh) + so + 16, bBH + gofs + 8);
        cp16(smem_u32(Bl) + so,      bBL + gofs);
        cp16(smem_u32(Bl) + so + 16, bBL + gofs + 8);
        CP_COMMIT();
        CP_WAIT0();
        __syncthreads();
        (void)sofs;

        #pragma unroll
        for (int kk = 0; kk < KC / 16; ++kk) {
            const int kb = kk * 16;
            uint32_t ahf[2][4], alf[2][4];
            #pragma unroll
            for (int mf = 0; mf < 2; ++mf) {
                const int m0 = wm * 32 + mf * 16;
                const int r0 = (m0 + gID) * SBF + kb + 2 * tig;
                const int r1 = (m0 + gID + 8) * SBF + kb + 2 * tig;
                ahf[mf][0] = *(const uint32_t*)(Ah + r0);
                ahf[mf][1] = *(const uint32_t*)(Ah + r1);
                ahf[mf][2] = *(const uint32_t*)(Ah + r0 + 8);
                ahf[mf][3] = *(const uint32_t*)(Ah + r1 + 8);
                alf[mf][0] = *(const uint32_t*)(Al + r0);
                alf[mf][1] = *(const uint32_t*)(Al + r1);
                alf[mf][2] = *(const uint32_t*)(Al + r0 + 8);
                alf[mf][3] = *(const uint32_t*)(Al + r1 + 8);
            }
            #pragma unroll
            for (int nf = 0; nf < 8; ++nf) {
                const int n0 = wn * 64 + nf * 8;
                const int rb = (n0 + gID) * SBF + kb + 2 * tig;
                uint32_t bh0 = *(const uint32_t*)(Bh + rb);
                uint32_t bh1 = *(const uint32_t*)(Bh + rb + 8);
                uint32_t bl0 = *(const uint32_t*)(Bl + rb);
                uint32_t bl1 = *(const uint32_t*)(Bl + rb + 8);
                #pragma unroll
                for (int mf = 0; mf < 2; ++mf) {
                    float* d = acc[mf][nf];
                    mma16(d[0], d[1], d[2], d[3],
                          ahf[mf][0], ahf[mf][1], ahf[mf][2], ahf[mf][3], bh0, bh1);
                    mma16(d[0], d[1], d[2], d[3],
                          ahf[mf][0], ahf[mf][1], ahf[mf][2], ahf[mf][3], bl0, bl1);
                    mma16(d[0], d[1], d[2], d[3],
                          alf[mf][0], alf[mf][1], alf[mf][2], alf[mf][3], bh0, bh1);
                }
            }
        }
        __syncthreads();
    }

    #pragma unroll
    for (int mf = 0; mf < 2; ++mf) {
        const int mrow = mtile * 128 + wm * 32 + mf * 16 + gID;
        #pragma unroll
        for (int nf = 0; nf < 8; ++nf) {
            const int ncol = ntile * 128 + wn * 64 + nf * 8 + 2 * tig;
            float* cp = g_scratch + ((size_t)b * 384 + mrow) * 256 + ncol;
            *(float2*)cp             = make_float2(acc[mf][nf][0], acc[mf][nf][1]);
            *(float2*)(cp + 8 * 256) = make_float2(acc[mf][nf][2], acc[mf][nf][3]);
        }
    }
}

// ---------------- Kernel 2: blocked causal scan (R13, unchanged) ----------------
#define SC_ROWS 16

__global__ __launch_bounds__(128)
void scan_kernel(float* __restrict__ out) {
    __shared__ float             tri[8][9];
    __shared__ __align__(16) u64 ych[8][SC_ROWS];
    __shared__ float             ser[8][SC_ROWS + 1];

    const int bb    = blockIdx.x;
    const int b     = bb >> 3;
    const int obase = (bb & 7) * SC_ROWS;
    const int tid   = threadIdx.x;

    const float* P0 = g_scratch + ((size_t)b * 384 + 256 + obase) * 256;
    const float* G  = g_scratch + (size_t)b * 384 * 256;
    float* outp     = out + (size_t)b * CM_T * CM_NOBS + obase;

    u64 pre[SC_ROWS];
    #pragma unroll
    for (int o = 0; o < SC_ROWS; ++o)
        pre[o] = *(const u64*)(P0 + o * 256 + 2 * tid);

    float trn = 0.f;
    if (tid < 64) trn = __ldg(&G[(size_t)(tid >> 3) * 256 + (tid & 7)]);
    u64 g2c[8];
    #pragma unroll
    for (int s = 0; s < 8; ++s)
        g2c[s] = *(const u64*)(G + (size_t)s * 256 + 2 * tid);

    #pragma unroll 1
    for (int k = 0; k < 32; ++k) {
        const int t0     = k * 8;
        const int towner = t0 >> 1;

        if (tid >= towner && tid < towner + 4) {
            const int s0 = (tid - towner) * 2;
            #pragma unroll
            for (int o = 0; o < SC_ROWS; ++o) {
                float2 v = upk2(pre[o]);
                ser[s0][o] = v.x; ser[s0 + 1][o] = v.y;
            }
        }
        if (tid < 64) tri[tid >> 3][tid & 7] = trn;
        __syncthreads();   // A

        const int t0n = (k < 31) ? t0 + 8 : t0;
        u64 g2n[8];
        #pragma unroll
        for (int s = 0; s < 8; ++s)
            g2n[s] = *(const u64*)(G + (size_t)(t0n + s) * 256 + 2 * tid);
        if (tid < 64) trn = __ldg(&G[(size_t)(t0n + (tid >> 3)) * 256 + t0n + (tid & 7)]);

        if (tid < SC_ROWS) {
            const int o = tid;
            float p[8];
            #pragma unroll
            for (int s = 0; s < 8; ++s) p[s] = ser[s][o];
            #pragma unroll
            for (int s = 0; s < 8; ++s) {
                const float y = sigmoidf_fast(p[s]);
                outp[(size_t)(t0 + s) * CM_NOBS + o] = y;
                const float c = ETA * y;
                ych[s][o] = pk2(c, c);
                #pragma unroll
                for (int s2 = s + 1; s2 < 8; ++s2)
                    p[s2] += c * tri[s][s2];
            }
        }
        __syncthreads();   // B

        if (tid >= towner + 4) {
            #pragma unroll
            for (int s = 0; s < 8; ++s) {
                const ulonglong2* cp = (const ulonglong2*)(&ych[s][0]);
                const u64 g = g2c[s];
                #pragma unroll
                for (int op = 0; op < SC_ROWS / 2; ++op) {
                    ulonglong2 c = cp[op];
                    pre[2 * op]     = ffma2(c.x, g, pre[2 * op]);
                    pre[2 * op + 1] = ffma2(c.y, g, pre[2 * op + 1]);
                }
            }
        }
        #pragma unroll
        for (int s = 0; s < 8; ++s) g2c[s] = g2n[s];
    }
}

// ---------------- launch ----------------
extern "C" void kernel_launch(void* const* d_in, const int* in_sizes, int n_in,
                              void* d_out, int out_size) {
    const float* X   = (const float*)d_in[0];
    const float* Wi  = (const float*)d_in[1];
    const int*   obs = (const int*)d_in[2];
    float*       out = (float*)d_out;

    prep_kernel<<<(NX4 + NW4) / 256, 256>>>(X, Wi, obs);
    gemm_kernel<<<dim3(CM_B, 5), 256>>>(0);
    scan_kernel<<<dim3(CM_B * 8), 128>>>(out);
}

// round 17
// speedup vs baseline: 1.1467x; 1.1467x over previous
#include <cuda_runtime.h>
#include <cstdint>

#define CM_B    64
#define CM_T    256
#define CM_NI   512
#define CM_NO   512
#define CM_NOBS 128
#define ETA     0.01f

typedef unsigned long long u64;

// Scratch: C[b][m][n], m<256 -> G[s=m][t=n]; m>=256 -> P0[o=m-256][t=n]
__device__ float g_scratch[(size_t)CM_B * 384 * 256];
// tf32-rounded operands (X in [b][t][k], W_obs gathered in [b][j][k])
__device__ float g_Xt[(size_t)CM_B * CM_T * CM_NI];
__device__ float g_Wt[(size_t)CM_B * CM_NOBS * CM_NI];

// ---------------- helpers ----------------
__device__ __forceinline__ u64 pk2(float lo, float hi) {
    u64 r; asm("mov.b64 %0, {%1, %2};" : "=l"(r) : "f"(lo), "f"(hi)); return r;
}
__device__ __forceinline__ float2 upk2(u64 v) {
    float2 f; asm("mov.b64 {%0, %1}, %2;" : "=f"(f.x), "=f"(f.y) : "l"(v)); return f;
}
__device__ __forceinline__ u64 ffma2(u64 a, u64 b, u64 c) {
    u64 d; asm("fma.rn.f32x2 %0, %1, %2, %3;" : "=l"(d) : "l"(a), "l"(b), "l"(c)); return d;
}
__device__ __forceinline__ float sigmoidf_fast(float v) {
    return __fdividef(1.0f, 1.0f + __expf(-v));
}
__device__ __forceinline__ uint32_t f2tf(float x) {
    uint32_t r; asm("cvt.rna.tf32.f32 %0, %1;" : "=r"(r) : "f"(x)); return r;
}
__device__ __forceinline__ uint32_t smem_u32(const void* p) {
    uint32_t a;
    asm("{ .reg .u64 t; cvta.to.shared.u64 t, %1; cvt.u32.u64 %0, t; }" : "=r"(a) : "l"(p));
    return a;
}
__device__ __forceinline__ void cp16(uint32_t saddr, const void* gptr) {
    asm volatile("cp.async.ca.shared.global [%0], [%1], 16;" :: "r"(saddr), "l"(gptr));
}
#define CP_COMMIT() asm volatile("cp.async.commit_group;" ::: "memory")

// mma m16n8k8 tf32, D += A*B
__device__ __forceinline__ void mma8(float& d0, float& d1, float& d2, float& d3,
                                     uint32_t a0, uint32_t a1, uint32_t a2, uint32_t a3,
                                     uint32_t b0, uint32_t b1) {
    asm volatile(
        "mma.sync.aligned.m16n8k8.row.col.f32.tf32.tf32.f32 "
        "{%0,%1,%2,%3}, {%4,%5,%6,%7}, {%8,%9}, {%0,%1,%2,%3};"
        : "+f"(d0), "+f"(d1), "+f"(d2), "+f"(d3)
        : "r"(a0), "r"(a1), "r"(a2), "r"(a3), "r"(b0), "r"(b1));
}

// ---------------- Kernel 0: prep — fp32 -> tf32(RN), W gathered ----------------
#define NX4 (CM_B * CM_T * CM_NI / 4)      // 2,097,152 float4 groups
#define NW4 (CM_B * CM_NOBS * CM_NI / 4)   // 1,048,576

__global__ __launch_bounds__(256)
void prep_kernel(const float* __restrict__ X,
                 const float* __restrict__ Wi,
                 const int*   __restrict__ obs) {
    const int idx = blockIdx.x * 256 + threadIdx.x;
    float4 v;
    float* dst;
    if (idx < NX4) {
        v   = __ldg((const float4*)X + idx);
        dst = g_Xt + (size_t)idx * 4;
    } else {
        const int id2 = idx - NX4;
        const int k4 = id2 & 127;
        const int j  = (id2 >> 7) & 127;
        const int b  = id2 >> 14;
        v   = __ldg((const float4*)(Wi + ((size_t)b * CM_NO + __ldg(&obs[j])) * CM_NI) + k4);
        dst = g_Wt + (size_t)id2 * 4;
    }
    uint4 o;
    o.x = f2tf(v.x); o.y = f2tf(v.y); o.z = f2tf(v.z); o.w = f2tf(v.w);
    *(uint4*)dst = o;
}

// ---------------- Kernel 1: batched GEMM C = [X;W_obs] * X^T (tf32 x1, pipelined) ----------------
#define KC   32
#define NCH  (CM_NI / KC)       // 16 chunks
#define SF   36                 // fp32 row stride (conflict-free fragments)
#define BUFF (128 * SF)         // floats per tile buffer
#define GEMM_SMEM (4 * BUFF * 4)   // A0,B0,A1,B1 = 73728 B

__constant__ int c_mt[5] = {0, 0, 1, 2, 2};
__constant__ int c_nt[5] = {0, 1, 1, 0, 1};

__global__ __launch_bounds__(256)
void gemm_kernel() {
    extern __shared__ __align__(16) float smemf[];

    const int b     = blockIdx.x;
    const int mtile = c_mt[blockIdx.y];
    const int ntile = c_nt[blockIdx.y];

    const int tid  = threadIdx.x;
    const int warp = tid >> 5, lane = tid & 31;
    const int wm   = warp >> 1, wn = warp & 1;      // 4x2 warps over 128x128
    const int gID  = lane >> 2, tig = lane & 3;

    // source row bases (W already gathered in j order)
    const float* aBase = (mtile < 2)
        ? g_Xt + ((size_t)b * CM_T + mtile * 128) * CM_NI
        : g_Wt + (size_t)b * CM_NOBS * CM_NI;
    const float* bBase = g_Xt + ((size_t)b * CM_T + ntile * 128) * CM_NI;

    // staging role: 2 threads per row, 16 floats (64B) each
    const int srow = tid >> 1;
    const int scq  = (tid & 1) * 16;
    const float* aRow = aBase + (size_t)srow * CM_NI + scq;
    const float* bRow = bBase + (size_t)srow * CM_NI + scq;
    const uint32_t soff = (uint32_t)((srow * SF + scq) * 4);
    const uint32_t sbase = smem_u32(smemf);

    auto stage = [&](int c, int buf) {
        const float* a = aRow + c * KC;
        const float* bb = bRow + c * KC;
        const uint32_t sa = sbase + (uint32_t)(2 * buf) * (BUFF * 4) + soff;
        const uint32_t sb = sa + BUFF * 4;
        cp16(sa,      a);      cp16(sa + 16, a + 4);
        cp16(sa + 32, a + 8);  cp16(sa + 48, a + 12);
        cp16(sb,      bb);     cp16(sb + 16, bb + 4);
        cp16(sb + 32, bb + 8); cp16(sb + 48, bb + 12);
        CP_COMMIT();
    };

    float acc[2][8][4];
    #pragma unroll
    for (int i = 0; i < 2; ++i)
        #pragma unroll
        for (int j = 0; j < 8; ++j)
            #pragma unroll
            for (int q = 0; q < 4; ++q) acc[i][j][q] = 0.f;

    stage(0, 0);

    for (int c = 0; c < NCH; ++c) {
        if (c + 1 < NCH) {
            stage(c + 1, (c + 1) & 1);
            asm volatile("cp.async.wait_group 1;" ::: "memory");
        } else {
            asm volatile("cp.async.wait_group 0;" ::: "memory");
        }
        __syncthreads();

        const float* A = smemf + 2 * (c & 1) * BUFF;
        const float* B = A + BUFF;

        #pragma unroll
        for (int kk = 0; kk < KC / 8; ++kk) {
            const int kb = kk * 8;
            uint32_t af[2][4];
            #pragma unroll
            for (int mf = 0; mf < 2; ++mf) {
                const int r0 = (wm * 32 + mf * 16 + gID) * SF + kb + tig;
                af[mf][0] = __float_as_uint(A[r0]);
                af[mf][1] = __float_as_uint(A[r0 + 8 * SF]);
                af[mf][2] = __float_as_uint(A[r0 + 4]);
                af[mf][3] = __float_as_uint(A[r0 + 8 * SF + 4]);
            }
            #pragma unroll
            for (int nf = 0; nf < 8; ++nf) {
                const int rb = (wn * 64 + nf * 8 + gID) * SF + kb + tig;
                const uint32_t b0 = __float_as_uint(B[rb]);
                const uint32_t b1 = __float_as_uint(B[rb + 4]);
                #pragma unroll
                for (int mf = 0; mf < 2; ++mf) {
                    float* d = acc[mf][nf];
                    mma8(d[0], d[1], d[2], d[3],
                         af[mf][0], af[mf][1], af[mf][2], af[mf][3], b0, b1);
                }
            }
        }
        __syncthreads();
    }

    #pragma unroll
    for (int mf = 0; mf < 2; ++mf) {
        const int mrow = mtile * 128 + wm * 32 + mf * 16 + gID;
        #pragma unroll
        for (int nf = 0; nf < 8; ++nf) {
            const int ncol = ntile * 128 + wn * 64 + nf * 8 + 2 * tig;
            float* cp = g_scratch + ((size_t)b * 384 + mrow) * 256 + ncol;
            *(float2*)cp             = make_float2(acc[mf][nf][0], acc[mf][nf][1]);
            *(float2*)(cp + 8 * 256) = make_float2(acc[mf][nf][2], acc[mf][nf][3]);
        }
    }
}

// ---------------- Kernel 2: blocked causal scan (R13, unchanged) ----------------
#define SC_ROWS 16

__global__ __launch_bounds__(128)
void scan_kernel(float* __restrict__ out) {
    __shared__ float             tri[8][9];
    __shared__ __align__(16) u64 ych[8][SC_ROWS];
    __shared__ float             ser[8][SC_ROWS + 1];

    const int bb    = blockIdx.x;
    const int b     = bb >> 3;
    const int obase = (bb & 7) * SC_ROWS;
    const int tid   = threadIdx.x;

    const float* P0 = g_scratch + ((size_t)b * 384 + 256 + obase) * 256;
    const float* G  = g_scratch + (size_t)b * 384 * 256;
    float* outp     = out + (size_t)b * CM_T * CM_NOBS + obase;

    u64 pre[SC_ROWS];
    #pragma unroll
    for (int o = 0; o < SC_ROWS; ++o)
        pre[o] = *(const u64*)(P0 + o * 256 + 2 * tid);

    float trn = 0.f;
    if (tid < 64) trn = __ldg(&G[(size_t)(tid >> 3) * 256 + (tid & 7)]);
    u64 g2c[8];
    #pragma unroll
    for (int s = 0; s < 8; ++s)
        g2c[s] = *(const u64*)(G + (size_t)s * 256 + 2 * tid);

    #pragma unroll 1
    for (int k = 0; k < 32; ++k) {
        const int t0     = k * 8;
        const int towner = t0 >> 1;

        if (tid >= towner && tid < towner + 4) {
            const int s0 = (tid - towner) * 2;
            #pragma unroll
            for (int o = 0; o < SC_ROWS; ++o) {
                float2 v = upk2(pre[o]);
                ser[s0][o] = v.x; ser[s0 + 1][o] = v.y;
            }
        }
        if (tid < 64) tri[tid >> 3][tid & 7] = trn;
        __syncthreads();   // A

        const int t0n = (k < 31) ? t0 + 8 : t0;
        u64 g2n[8];
        #pragma unroll
        for (int s = 0; s < 8; ++s)
            g2n[s] = *(const u64*)(G + (size_t)(t0n + s) * 256 + 2 * tid);
        if (tid < 64) trn = __ldg(&G[(size_t)(t0n + (tid >> 3)) * 256 + t0n + (tid & 7)]);

        if (tid < SC_ROWS) {
            const int o = tid;
            float p[8];
            #pragma unroll
            for (int s = 0; s < 8; ++s) p[s] = ser[s][o];
            #pragma unroll
            for (int s = 0; s < 8; ++s) {
                const float y = sigmoidf_fast(p[s]);
                outp[(size_t)(t0 + s) * CM_NOBS + o] = y;
                const float c = ETA * y;
                ych[s][o] = pk2(c, c);
                #pragma unroll
                for (int s2 = s + 1; s2 < 8; ++s2)
                    p[s2] += c * tri[s][s2];
            }
        }
        __syncthreads();   // B

        if (tid >= towner + 4) {
            #pragma unroll
            for (int s = 0; s < 8; ++s) {
                const ulonglong2* cp = (const ulonglong2*)(&ych[s][0]);
                const u64 g = g2c[s];
                #pragma unroll
                for (int op = 0; op < SC_ROWS / 2; ++op) {
                    ulonglong2 c = cp[op];
                    pre[2 * op]     = ffma2(c.x, g, pre[2 * op]);
                    pre[2 * op + 1] = ffma2(c.y, g, pre[2 * op + 1]);
                }
            }
        }
        #pragma unroll
        for (int s = 0; s < 8; ++s) g2c[s] = g2n[s];
    }
}

// ---------------- launch ----------------
extern "C" void kernel_launch(void* const* d_in, const int* in_sizes, int n_in,
                              void* d_out, int out_size) {
    const float* X   = (const float*)d_in[0];
    const float* Wi  = (const float*)d_in[1];
    const int*   obs = (const int*)d_in[2];
    float*       out = (float*)d_out;

    static int configured = 0;
    if (!configured) {
        cudaFuncSetAttribute(gemm_kernel,
                             cudaFuncAttributeMaxDynamicSharedMemorySize, GEMM_SMEM);
        configured = 1;
    }

    prep_kernel<<<(NX4 + NW4) / 256, 256>>>(X, Wi, obs);
    gemm_kernel<<<dim3(CM_B, 5), 256, GEMM_SMEM>>>();
    scan_kernel<<<dim3(CM_B * 8), 128>>>(out);
}